// round 5
// baseline (speedup 1.0000x reference)
#include <cuda_runtime.h>
#include <cuda_fp16.h>

#define N_NODES   8192
#define B_BATCH   2
#define D_IN      64
#define D_OUT     32
#define K_ITERS   4
#define C_CH      (K_ITERS * D_OUT)   // 128
#define ALPHA_F   0.1f
#define OMA_F     0.9f
#define BN_EPS_F  1e-5f
#define MAX_NNZ   128                 // capacity; usable 112 + 16 prefetch slack
#define CNT_CAP   112
#define NSAMP     (B_BATCH * N_NODES)
#define SPMM_BLOCKS 2048               // 4 rows per block, warp per row

// ---------------- device scratch ----------------
__device__ __half2 g_hkA[N_NODES * D_OUT];               // ping [n][f] -> (b0,b1)
__device__ __half2 g_hkB[N_NODES * D_OUT];               // pong
__device__ float2  g_h0 [N_NODES * D_OUT];               // alpha*(x0@W0)
__device__ int4    g_cv4[(size_t)N_NODES * MAX_NNZ / 2]; // {col,val,col,val}
__device__ int     g_cnt[N_NODES];                       // padded to mult of 16
__device__ float   g_y  [(size_t)B_BATCH * N_NODES * C_CH];
__device__ float   g_psum[K_ITERS * SPMM_BLOCKS * D_OUT];
__device__ float   g_psq [K_ITERS * SPMM_BLOCKS * D_OUT];
__device__ float   g_scale[C_CH];
__device__ float   g_shift[C_CH];

// ---------------- 1) projections, both batches per thread ----------------
__global__ void gemm_kernel(const float* __restrict__ x,
                            const float* __restrict__ x0,
                            const float* __restrict__ W,
                            const float* __restrict__ W0) {
    __shared__ float Ws [D_IN * D_OUT];
    __shared__ float W0s[D_IN * D_OUT];
    __shared__ float xa [8][D_IN], xb [8][D_IN];
    __shared__ float x0a[8][D_IN], x0b[8][D_IN];

    const int t = threadIdx.x;
    const int rowBase = blockIdx.x * 8;

    for (int i = t; i < D_IN * D_OUT; i += 256) { Ws[i] = W[i]; W0s[i] = W0[i]; }
    for (int i = t; i < 8 * D_IN; i += 256) {
        const int r = rowBase + (i >> 6);
        const int d = i & 63;
        xa [i >> 6][d] = x [(size_t)r * D_IN + d];
        xb [i >> 6][d] = x [(size_t)(N_NODES + r) * D_IN + d];
        x0a[i >> 6][d] = x0[(size_t)r * D_IN + d];
        x0b[i >> 6][d] = x0[(size_t)(N_NODES + r) * D_IN + d];
    }
    __syncthreads();

    const int rr = t >> 5;
    const int f  = t & 31;
    const int row = rowBase + rr;
    float ha = 0.f, hb = 0.f, za = 0.f, zb = 0.f;
#pragma unroll
    for (int d = 0; d < D_IN; ++d) {
        const float w  = Ws [d * D_OUT + f];
        const float w0 = W0s[d * D_OUT + f];
        ha = fmaf(xa [rr][d], w,  ha);
        hb = fmaf(xb [rr][d], w,  hb);
        za = fmaf(x0a[rr][d], w0, za);
        zb = fmaf(x0b[rr][d], w0, zb);
    }
    g_hkA[row * D_OUT + f] = __floats2half2_rn(ha, hb);
    g_h0 [row * D_OUT + f] = make_float2(za * ALPHA_F, zb * ALPHA_F);
}

// ---------------- 2) dense -> padded packed CSR ----------------
// One "any" ballot per 128-col chunk; element ballots only on nonzero chunks
// (~21% of chunks at 0.5% density). Rows padded to mult of 16 + 16 slack.
__global__ void csr_kernel(const float* __restrict__ adj) {
    const int warp = (blockIdx.x * blockDim.x + threadIdx.x) >> 5;
    const int lane = threadIdx.x & 31;
    if (warp >= N_NODES) return;

    const float4* row = (const float4*)(adj + (size_t)warp * N_NODES);
    int2* out = (int2*)&g_cv4[(size_t)warp * (MAX_NNZ / 2)];
    int base = 0;

    for (int ch = 0; ch < N_NODES / 128; ch += 2) {
        float4 vA = __ldcs(&row[ch * 32 + lane]);
        float4 vB = __ldcs(&row[(ch + 1) * 32 + lane]);
#pragma unroll
        for (int half = 0; half < 2; ++half) {
            const float4 v = half ? vB : vA;
            const bool any = (v.x != 0.f) | (v.y != 0.f) | (v.z != 0.f) | (v.w != 0.f);
            const unsigned am = __ballot_sync(0xffffffffu, any);
            if (am == 0u) continue;                 // uniform branch
            const float e[4] = {v.x, v.y, v.z, v.w};
#pragma unroll
            for (int k = 0; k < 4; ++k) {
                const bool nz = (e[k] != 0.0f);
                const unsigned m = __ballot_sync(0xffffffffu, nz);
                if (nz) {
                    int pos = base + __popc(m & ((1u << lane) - 1u));
                    if (pos < CNT_CAP)
                        out[pos] = make_int2((ch + half) * 128 + lane * 4 + k,
                                             __float_as_int(e[k] * OMA_F));
                }
                base += __popc(m);
            }
        }
    }
    int cnt  = base < CNT_CAP ? base : CNT_CAP;
    int cntp = (cnt + 15) & ~15;
    for (int j = cnt + lane; j < cntp + 16; j += 32)
        out[j] = make_int2(0, 0);                    // val = 0 padding
    if (lane == 0) g_cnt[warp] = cntp;
}

// ---------------- 3) SpMM iterate: 16 nnz/iter, meta prefetch, BN partials ----
__global__ void spmm_kernel(const __half2* __restrict__ src,
                            __half2* __restrict__ dst, int kslice) {
    __shared__ float shs[4][32];
    __shared__ float shq[4][32];

    const int warp = threadIdx.x >> 5;
    const int lane = threadIdx.x & 31;
    const int r    = blockIdx.x * 4 + warp;

    const int4* __restrict__ cv = g_cv4 + (size_t)r * (MAX_NNZ / 2);
    const int nIt = g_cnt[r] >> 4;            // groups of 16 nnz (>=1: self loop)

    const float2 h0 = __ldg(&g_h0[r * D_OUT + lane]);
    float acc0 = h0.x, acc1 = h0.y;

    int4 m0 = __ldg(&cv[0]), m1 = __ldg(&cv[1]), m2 = __ldg(&cv[2]), m3 = __ldg(&cv[3]);
    int4 m4 = __ldg(&cv[4]), m5 = __ldg(&cv[5]), m6 = __ldg(&cv[6]), m7 = __ldg(&cv[7]);

    for (int it = 0; it < nIt; ++it) {
        // 16 independent gathers (one 128B line each)
        const __half2 g0  = __ldg(&src[m0.x * D_OUT + lane]);
        const __half2 g1  = __ldg(&src[m0.z * D_OUT + lane]);
        const __half2 g2  = __ldg(&src[m1.x * D_OUT + lane]);
        const __half2 g3  = __ldg(&src[m1.z * D_OUT + lane]);
        const __half2 g4  = __ldg(&src[m2.x * D_OUT + lane]);
        const __half2 g5  = __ldg(&src[m2.z * D_OUT + lane]);
        const __half2 g6  = __ldg(&src[m3.x * D_OUT + lane]);
        const __half2 g7  = __ldg(&src[m3.z * D_OUT + lane]);
        const __half2 g8  = __ldg(&src[m4.x * D_OUT + lane]);
        const __half2 g9  = __ldg(&src[m4.z * D_OUT + lane]);
        const __half2 g10 = __ldg(&src[m5.x * D_OUT + lane]);
        const __half2 g11 = __ldg(&src[m5.z * D_OUT + lane]);
        const __half2 g12 = __ldg(&src[m6.x * D_OUT + lane]);
        const __half2 g13 = __ldg(&src[m6.z * D_OUT + lane]);
        const __half2 g14 = __ldg(&src[m7.x * D_OUT + lane]);
        const __half2 g15 = __ldg(&src[m7.z * D_OUT + lane]);

        const float v0  = __int_as_float(m0.y), v1  = __int_as_float(m0.w);
        const float v2  = __int_as_float(m1.y), v3  = __int_as_float(m1.w);
        const float v4  = __int_as_float(m2.y), v5  = __int_as_float(m2.w);
        const float v6  = __int_as_float(m3.y), v7  = __int_as_float(m3.w);
        const float v8  = __int_as_float(m4.y), v9  = __int_as_float(m4.w);
        const float v10 = __int_as_float(m5.y), v11 = __int_as_float(m5.w);
        const float v12 = __int_as_float(m6.y), v13 = __int_as_float(m6.w);
        const float v14 = __int_as_float(m7.y), v15 = __int_as_float(m7.w);

        // prefetch next group's metadata (slack region -> always safe)
        const int nb = (it + 1) * 8;
        m0 = __ldg(&cv[nb + 0]); m1 = __ldg(&cv[nb + 1]);
        m2 = __ldg(&cv[nb + 2]); m3 = __ldg(&cv[nb + 3]);
        m4 = __ldg(&cv[nb + 4]); m5 = __ldg(&cv[nb + 5]);
        m6 = __ldg(&cv[nb + 6]); m7 = __ldg(&cv[nb + 7]);

        float2 f;
        f = __half22float2(g0);  acc0 = fmaf(v0,  f.x, acc0); acc1 = fmaf(v0,  f.y, acc1);
        f = __half22float2(g1);  acc0 = fmaf(v1,  f.x, acc0); acc1 = fmaf(v1,  f.y, acc1);
        f = __half22float2(g2);  acc0 = fmaf(v2,  f.x, acc0); acc1 = fmaf(v2,  f.y, acc1);
        f = __half22float2(g3);  acc0 = fmaf(v3,  f.x, acc0); acc1 = fmaf(v3,  f.y, acc1);
        f = __half22float2(g4);  acc0 = fmaf(v4,  f.x, acc0); acc1 = fmaf(v4,  f.y, acc1);
        f = __half22float2(g5);  acc0 = fmaf(v5,  f.x, acc0); acc1 = fmaf(v5,  f.y, acc1);
        f = __half22float2(g6);  acc0 = fmaf(v6,  f.x, acc0); acc1 = fmaf(v6,  f.y, acc1);
        f = __half22float2(g7);  acc0 = fmaf(v7,  f.x, acc0); acc1 = fmaf(v7,  f.y, acc1);
        f = __half22float2(g8);  acc0 = fmaf(v8,  f.x, acc0); acc1 = fmaf(v8,  f.y, acc1);
        f = __half22float2(g9);  acc0 = fmaf(v9,  f.x, acc0); acc1 = fmaf(v9,  f.y, acc1);
        f = __half22float2(g10); acc0 = fmaf(v10, f.x, acc0); acc1 = fmaf(v10, f.y, acc1);
        f = __half22float2(g11); acc0 = fmaf(v11, f.x, acc0); acc1 = fmaf(v11, f.y, acc1);
        f = __half22float2(g12); acc0 = fmaf(v12, f.x, acc0); acc1 = fmaf(v12, f.y, acc1);
        f = __half22float2(g13); acc0 = fmaf(v13, f.x, acc0); acc1 = fmaf(v13, f.y, acc1);
        f = __half22float2(g14); acc0 = fmaf(v14, f.x, acc0); acc1 = fmaf(v14, f.y, acc1);
        f = __half22float2(g15); acc0 = fmaf(v15, f.x, acc0); acc1 = fmaf(v15, f.y, acc1);
    }

    dst[r * D_OUT + lane] = __floats2half2_rn(acc0, acc1);
    g_y[(size_t)r * C_CH + kslice * D_OUT + lane]             = acc0;
    g_y[(size_t)(N_NODES + r) * C_CH + kslice * D_OUT + lane] = acc1;

    shs[warp][lane] = acc0 + acc1;
    shq[warp][lane] = fmaf(acc0, acc0, acc1 * acc1);
    __syncthreads();
    if (warp == 0) {
        float s = shs[0][lane] + shs[1][lane] + shs[2][lane] + shs[3][lane];
        g_psum[(kslice * SPMM_BLOCKS + blockIdx.x) * D_OUT + lane] = s;
    }
    if (warp == 1) {
        float q = shq[0][lane] + shq[1][lane] + shq[2][lane] + shq[3][lane];
        g_psq[(kslice * SPMM_BLOCKS + blockIdx.x) * D_OUT + lane] = q;
    }
}

// ---------------- 4) finalize BN params ----------------
__global__ void bn_final_kernel(const float* __restrict__ gamma,
                                const float* __restrict__ beta) {
    __shared__ float ss[1024], qq[1024];
    const int c = threadIdx.x & 127;            // channel
    const int h = threadIdx.x >> 7;             // 0..7
    const int slice = c >> 5, lane = c & 31;

    float s = 0.f, q = 0.f;
    for (int b = h; b < SPMM_BLOCKS; b += 8) {
        s += g_psum[(slice * SPMM_BLOCKS + b) * D_OUT + lane];
        q += g_psq [(slice * SPMM_BLOCKS + b) * D_OUT + lane];
    }
    ss[threadIdx.x] = s;
    qq[threadIdx.x] = q;
    __syncthreads();
    if (h == 0) {
        s = 0.f; q = 0.f;
#pragma unroll
        for (int w = 0; w < 8; ++w) { s += ss[c + 128 * w]; q += qq[c + 128 * w]; }
        const float inv  = 1.0f / (float)NSAMP;
        const float mean = s * inv;
        const float var  = q * inv - mean * mean;
        const float sc   = gamma[c] * rsqrtf(var + BN_EPS_F);
        g_scale[c] = sc;
        g_shift[c] = beta[c] - mean * sc;
    }
}

// ---------------- 5) normalize + ReLU ----------------
__global__ void norm_kernel(float* __restrict__ out) {
    const int idx = blockIdx.x * blockDim.x + threadIdx.x;   // float4 index
    float4 v = ((const float4*)g_y)[idx];
    const int c0 = (idx & 31) * 4;
    v.x = fmaxf(0.f, fmaf(v.x, g_scale[c0 + 0], g_shift[c0 + 0]));
    v.y = fmaxf(0.f, fmaf(v.y, g_scale[c0 + 1], g_shift[c0 + 1]));
    v.z = fmaxf(0.f, fmaf(v.z, g_scale[c0 + 2], g_shift[c0 + 2]));
    v.w = fmaxf(0.f, fmaf(v.w, g_scale[c0 + 3], g_shift[c0 + 3]));
    ((float4*)out)[idx] = v;
}

// ---------------- launch ----------------
extern "C" void kernel_launch(void* const* d_in, const int* in_sizes, int n_in,
                              void* d_out, int out_size) {
    const float* x     = (const float*)d_in[0];
    const float* x0    = (const float*)d_in[1];
    const float* adj   = (const float*)d_in[2];
    const float* W     = (const float*)d_in[3];
    const float* W0    = (const float*)d_in[4];
    const float* gamma = (const float*)d_in[5];
    const float* beta  = (const float*)d_in[6];
    float* out = (float*)d_out;

    __half2 *hkA, *hkB;
    cudaGetSymbolAddress((void**)&hkA, g_hkA);
    cudaGetSymbolAddress((void**)&hkB, g_hkB);

    gemm_kernel<<<N_NODES / 8, 256>>>(x, x0, W, W0);
    csr_kernel<<<N_NODES / 8, 256>>>(adj);

    spmm_kernel<<<SPMM_BLOCKS, 128>>>(hkA, hkB, 0);
    spmm_kernel<<<SPMM_BLOCKS, 128>>>(hkB, hkA, 1);
    spmm_kernel<<<SPMM_BLOCKS, 128>>>(hkA, hkB, 2);
    spmm_kernel<<<SPMM_BLOCKS, 128>>>(hkB, hkA, 3);

    bn_final_kernel<<<1, 1024>>>(gamma, beta);
    norm_kernel<<<(NSAMP * C_CH / 4) / 256, 256>>>(out);
}

// round 6
// speedup vs baseline: 1.0770x; 1.0770x over previous
#include <cuda_runtime.h>
#include <cuda_fp16.h>

#define N_NODES   8192
#define B_BATCH   2
#define D_IN      64
#define D_OUT     32
#define K_ITERS   4
#define C_CH      (K_ITERS * D_OUT)   // 128
#define ALPHA_F   0.1f
#define OMA_F     0.9f
#define BN_EPS_F  1e-5f
#define MAX_NNZ   128
#define NSAMP     (B_BATCH * N_NODES)
#define SPMM_BLOCKS 1024               // 8 rows per block, warp per row
#define GEMM_BLOCKS 1024               // 8 node-rows per block

// ---------------- device scratch ----------------
__device__ __half2 g_hkA[N_NODES * D_OUT];               // ping [n][f] -> (b0,b1)
__device__ __half2 g_hkB[N_NODES * D_OUT];               // pong
__device__ float2  g_h0 [N_NODES * D_OUT];               // alpha*(x0@W0)
__device__ int4    g_cv4[(size_t)N_NODES * MAX_NNZ / 2]; // {col,val,col,val}
__device__ int     g_cnt[N_NODES];                       // padded to mult of 8
__device__ float   g_y  [(size_t)B_BATCH * N_NODES * C_CH];
__device__ float   g_psum[K_ITERS * SPMM_BLOCKS * D_OUT];
__device__ float   g_psq [K_ITERS * SPMM_BLOCKS * D_OUT];
__device__ float   g_scale[C_CH];
__device__ float   g_shift[C_CH];

// ---------------- 1) fused: projections (blocks < GEMM_BLOCKS) + CSR build ----
__global__ void pre_kernel(const float* __restrict__ x,
                           const float* __restrict__ x0,
                           const float* __restrict__ W,
                           const float* __restrict__ W0,
                           const float* __restrict__ adj) {
    if (blockIdx.x < GEMM_BLOCKS) {
        // ---- GEMM part: 8 node rows, both batches ----
        __shared__ float Ws [D_IN * D_OUT];
        __shared__ float W0s[D_IN * D_OUT];
        __shared__ float xa [8][D_IN], xb [8][D_IN];
        __shared__ float x0a[8][D_IN], x0b[8][D_IN];

        const int t = threadIdx.x;
        const int rowBase = blockIdx.x * 8;

        for (int i = t; i < D_IN * D_OUT; i += 256) { Ws[i] = W[i]; W0s[i] = W0[i]; }
        for (int i = t; i < 8 * D_IN; i += 256) {
            const int r = rowBase + (i >> 6);
            const int d = i & 63;
            xa [i >> 6][d] = x [(size_t)r * D_IN + d];
            xb [i >> 6][d] = x [(size_t)(N_NODES + r) * D_IN + d];
            x0a[i >> 6][d] = x0[(size_t)r * D_IN + d];
            x0b[i >> 6][d] = x0[(size_t)(N_NODES + r) * D_IN + d];
        }
        __syncthreads();

        const int rr = t >> 5;
        const int f  = t & 31;
        const int row = rowBase + rr;
        float ha = 0.f, hb = 0.f, za = 0.f, zb = 0.f;
#pragma unroll
        for (int d = 0; d < D_IN; ++d) {
            const float w  = Ws [d * D_OUT + f];
            const float w0 = W0s[d * D_OUT + f];
            ha = fmaf(xa [rr][d], w,  ha);
            hb = fmaf(xb [rr][d], w,  hb);
            za = fmaf(x0a[rr][d], w0, za);
            zb = fmaf(x0b[rr][d], w0, zb);
        }
        g_hkA[row * D_OUT + f] = __floats2half2_rn(ha, hb);
        g_h0 [row * D_OUT + f] = make_float2(za * ALPHA_F, zb * ALPHA_F);
    } else {
        // ---- CSR part: warp per adjacency row ----
        const int warp = ((blockIdx.x - GEMM_BLOCKS) * 256 + threadIdx.x) >> 5;
        const int lane = threadIdx.x & 31;

        const float4* row = (const float4*)(adj + (size_t)warp * N_NODES);
        int2* out = (int2*)&g_cv4[(size_t)warp * (MAX_NNZ / 2)];
        int base = 0;

        for (int ch = 0; ch < N_NODES / 128; ch += 2) {
            float4 vA = __ldcs(&row[ch * 32 + lane]);
            float4 vB = __ldcs(&row[(ch + 1) * 32 + lane]);
#pragma unroll
            for (int half = 0; half < 2; ++half) {
                const float4 v = half ? vB : vA;
                const bool any = (v.x != 0.f) | (v.y != 0.f) | (v.z != 0.f) | (v.w != 0.f);
                const unsigned am = __ballot_sync(0xffffffffu, any);
                if (am == 0u) continue;                 // uniform branch
                const float e[4] = {v.x, v.y, v.z, v.w};
#pragma unroll
                for (int k = 0; k < 4; ++k) {
                    const bool nz = (e[k] != 0.0f);
                    const unsigned m = __ballot_sync(0xffffffffu, nz);
                    if (nz) {
                        int pos = base + __popc(m & ((1u << lane) - 1u));
                        if (pos < MAX_NNZ)
                            out[pos] = make_int2((ch + half) * 128 + lane * 4 + k,
                                                 __float_as_int(e[k] * OMA_F));
                    }
                    base += __popc(m);
                }
            }
        }
        int cnt  = base < MAX_NNZ ? base : MAX_NNZ;
        int cntp = (cnt + 7) & ~7;
        for (int j = cnt + lane; j < cntp; j += 32)
            out[j] = make_int2(0, 0);                    // val = 0 padding
        if (lane == 0) g_cnt[warp] = cntp;
    }
}

// ---------------- 2) SpMM iterate: smem-staged meta + fused BN partials ------
__global__ void spmm_kernel(const __half2* __restrict__ src,
                            __half2* __restrict__ dst, int kslice) {
    __shared__ int4  meta[8][MAX_NNZ / 2];     // 8 KB: per-warp row metadata
    __shared__ float shs[8][32];
    __shared__ float shq[8][32];

    const int warp = threadIdx.x >> 5;
    const int lane = threadIdx.x & 31;
    const int r    = blockIdx.x * 8 + warp;

    // bulk-stage this row's (col,val) pairs: 2 coalesced int4 loads per lane
    const int4* __restrict__ cv = g_cv4 + (size_t)r * (MAX_NNZ / 2);
    meta[warp][lane]      = __ldg(&cv[lane]);
    meta[warp][lane + 32] = __ldg(&cv[lane + 32]);

    const int nIt = g_cnt[r] >> 3;             // groups of 8 nnz (>=1: self loop)
    const float2 h0 = __ldg(&g_h0[r * D_OUT + lane]);
    float acc0 = h0.x, acc1 = h0.y;
    __syncwarp();

    for (int it = 0; it < nIt; ++it) {
        const int4 a = meta[warp][it * 4 + 0];   // uniform LDS.128
        const int4 b = meta[warp][it * 4 + 1];
        const int4 c = meta[warp][it * 4 + 2];
        const int4 d = meta[warp][it * 4 + 3];

        const __half2 g0 = __ldg(&src[a.x * D_OUT + lane]);
        const __half2 g1 = __ldg(&src[a.z * D_OUT + lane]);
        const __half2 g2 = __ldg(&src[b.x * D_OUT + lane]);
        const __half2 g3 = __ldg(&src[b.z * D_OUT + lane]);
        const __half2 g4 = __ldg(&src[c.x * D_OUT + lane]);
        const __half2 g5 = __ldg(&src[c.z * D_OUT + lane]);
        const __half2 g6 = __ldg(&src[d.x * D_OUT + lane]);
        const __half2 g7 = __ldg(&src[d.z * D_OUT + lane]);

        float2 f;
        f = __half22float2(g0); acc0 = fmaf(__int_as_float(a.y), f.x, acc0); acc1 = fmaf(__int_as_float(a.y), f.y, acc1);
        f = __half22float2(g1); acc0 = fmaf(__int_as_float(a.w), f.x, acc0); acc1 = fmaf(__int_as_float(a.w), f.y, acc1);
        f = __half22float2(g2); acc0 = fmaf(__int_as_float(b.y), f.x, acc0); acc1 = fmaf(__int_as_float(b.y), f.y, acc1);
        f = __half22float2(g3); acc0 = fmaf(__int_as_float(b.w), f.x, acc0); acc1 = fmaf(__int_as_float(b.w), f.y, acc1);
        f = __half22float2(g4); acc0 = fmaf(__int_as_float(c.y), f.x, acc0); acc1 = fmaf(__int_as_float(c.y), f.y, acc1);
        f = __half22float2(g5); acc0 = fmaf(__int_as_float(c.w), f.x, acc0); acc1 = fmaf(__int_as_float(c.w), f.y, acc1);
        f = __half22float2(g6); acc0 = fmaf(__int_as_float(d.y), f.x, acc0); acc1 = fmaf(__int_as_float(d.y), f.y, acc1);
        f = __half22float2(g7); acc0 = fmaf(__int_as_float(d.w), f.x, acc0); acc1 = fmaf(__int_as_float(d.w), f.y, acc1);
    }

    dst[r * D_OUT + lane] = __floats2half2_rn(acc0, acc1);
    g_y[(size_t)r * C_CH + kslice * D_OUT + lane]             = acc0;
    g_y[(size_t)(N_NODES + r) * C_CH + kslice * D_OUT + lane] = acc1;

    shs[warp][lane] = acc0 + acc1;
    shq[warp][lane] = fmaf(acc0, acc0, acc1 * acc1);
    __syncthreads();
    if (warp == 0) {
        float s = 0.f;
#pragma unroll
        for (int w = 0; w < 8; ++w) s += shs[w][lane];
        g_psum[(kslice * SPMM_BLOCKS + blockIdx.x) * D_OUT + lane] = s;
    }
    if (warp == 1) {
        float q = 0.f;
#pragma unroll
        for (int w = 0; w < 8; ++w) q += shq[w][lane];
        g_psq[(kslice * SPMM_BLOCKS + blockIdx.x) * D_OUT + lane] = q;
    }
}

// ---------------- 3) finalize BN params ----------------
__global__ void bn_final_kernel(const float* __restrict__ gamma,
                                const float* __restrict__ beta) {
    __shared__ float ss[1024], qq[1024];
    const int c = threadIdx.x & 127;            // channel
    const int h = threadIdx.x >> 7;             // 0..7
    const int slice = c >> 5, lane = c & 31;

    float s = 0.f, q = 0.f;
    for (int b = h; b < SPMM_BLOCKS; b += 8) {
        s += g_psum[(slice * SPMM_BLOCKS + b) * D_OUT + lane];
        q += g_psq [(slice * SPMM_BLOCKS + b) * D_OUT + lane];
    }
    ss[threadIdx.x] = s;
    qq[threadIdx.x] = q;
    __syncthreads();
    if (h == 0) {
        s = 0.f; q = 0.f;
#pragma unroll
        for (int w = 0; w < 8; ++w) { s += ss[c + 128 * w]; q += qq[c + 128 * w]; }
        const float inv  = 1.0f / (float)NSAMP;
        const float mean = s * inv;
        const float var  = q * inv - mean * mean;
        const float sc   = gamma[c] * rsqrtf(var + BN_EPS_F);
        g_scale[c] = sc;
        g_shift[c] = beta[c] - mean * sc;
    }
}

// ---------------- 4) normalize + ReLU ----------------
__global__ void norm_kernel(float* __restrict__ out) {
    const int idx = blockIdx.x * blockDim.x + threadIdx.x;   // float4 index
    float4 v = ((const float4*)g_y)[idx];
    const int c0 = (idx & 31) * 4;
    v.x = fmaxf(0.f, fmaf(v.x, g_scale[c0 + 0], g_shift[c0 + 0]));
    v.y = fmaxf(0.f, fmaf(v.y, g_scale[c0 + 1], g_shift[c0 + 1]));
    v.z = fmaxf(0.f, fmaf(v.z, g_scale[c0 + 2], g_shift[c0 + 2]));
    v.w = fmaxf(0.f, fmaf(v.w, g_scale[c0 + 3], g_shift[c0 + 3]));
    ((float4*)out)[idx] = v;
}

// ---------------- launch ----------------
extern "C" void kernel_launch(void* const* d_in, const int* in_sizes, int n_in,
                              void* d_out, int out_size) {
    const float* x     = (const float*)d_in[0];
    const float* x0    = (const float*)d_in[1];
    const float* adj   = (const float*)d_in[2];
    const float* W     = (const float*)d_in[3];
    const float* W0    = (const float*)d_in[4];
    const float* gamma = (const float*)d_in[5];
    const float* beta  = (const float*)d_in[6];
    float* out = (float*)d_out;

    __half2 *hkA, *hkB;
    cudaGetSymbolAddress((void**)&hkA, g_hkA);
    cudaGetSymbolAddress((void**)&hkB, g_hkB);

    pre_kernel<<<GEMM_BLOCKS + N_NODES / 8, 256>>>(x, x0, W, W0, adj);

    spmm_kernel<<<SPMM_BLOCKS, 256>>>(hkA, hkB, 0);
    spmm_kernel<<<SPMM_BLOCKS, 256>>>(hkB, hkA, 1);
    spmm_kernel<<<SPMM_BLOCKS, 256>>>(hkA, hkB, 2);
    spmm_kernel<<<SPMM_BLOCKS, 256>>>(hkB, hkA, 3);

    bn_final_kernel<<<1, 1024>>>(gamma, beta);
    norm_kernel<<<(NSAMP * C_CH / 4) / 256, 256>>>(out);
}

// round 7
// speedup vs baseline: 1.1182x; 1.0382x over previous
#include <cuda_runtime.h>
#include <cuda_fp16.h>

#define N_NODES   8192
#define B_BATCH   2
#define D_IN      64
#define D_OUT     32
#define K_ITERS   4
#define C_CH      (K_ITERS * D_OUT)   // 128
#define ALPHA_F   0.1f
#define OMA_F     0.9f
#define BN_EPS_F  1e-5f
#define MAX_NNZ   128
#define NSAMP     (B_BATCH * N_NODES)
#define SPMM_BLOCKS 1024               // 8 rows per block, warp per row

// ---------------- device scratch ----------------
__device__ __half2 g_hkA[N_NODES * D_OUT];               // ping [n][f] -> (b0,b1)
__device__ __half2 g_hkB[N_NODES * D_OUT];               // pong
__device__ float2  g_h0 [N_NODES * D_OUT];               // alpha*(x0@W0)
__device__ int4    g_cv4[(size_t)N_NODES * MAX_NNZ / 2]; // {col,val,col,val}
__device__ int     g_cnt[N_NODES];                       // padded to mult of 8
__device__ float   g_y  [(size_t)B_BATCH * N_NODES * C_CH];
__device__ float   g_psum[K_ITERS * SPMM_BLOCKS * D_OUT];
__device__ float   g_psq [K_ITERS * SPMM_BLOCKS * D_OUT];
__device__ float   g_scale[C_CH];
__device__ float   g_shift[C_CH];

// ---------------- 1) projections, both batches per thread ----------------
__global__ void gemm_kernel(const float* __restrict__ x,
                            const float* __restrict__ x0,
                            const float* __restrict__ W,
                            const float* __restrict__ W0) {
    __shared__ float Ws [D_IN * D_OUT];
    __shared__ float W0s[D_IN * D_OUT];
    __shared__ float xa [8][D_IN], xb [8][D_IN];
    __shared__ float x0a[8][D_IN], x0b[8][D_IN];

    const int t = threadIdx.x;
    const int rowBase = blockIdx.x * 8;

    for (int i = t; i < D_IN * D_OUT; i += 256) { Ws[i] = W[i]; W0s[i] = W0[i]; }
    for (int i = t; i < 8 * D_IN; i += 256) {
        const int r = rowBase + (i >> 6);
        const int d = i & 63;
        xa [i >> 6][d] = x [(size_t)r * D_IN + d];
        xb [i >> 6][d] = x [(size_t)(N_NODES + r) * D_IN + d];
        x0a[i >> 6][d] = x0[(size_t)r * D_IN + d];
        x0b[i >> 6][d] = x0[(size_t)(N_NODES + r) * D_IN + d];
    }
    __syncthreads();

    const int rr = t >> 5;
    const int f  = t & 31;
    const int row = rowBase + rr;
    float ha = 0.f, hb = 0.f, za = 0.f, zb = 0.f;
#pragma unroll
    for (int d = 0; d < D_IN; ++d) {
        const float w  = Ws [d * D_OUT + f];
        const float w0 = W0s[d * D_OUT + f];
        ha = fmaf(xa [rr][d], w,  ha);
        hb = fmaf(xb [rr][d], w,  hb);
        za = fmaf(x0a[rr][d], w0, za);
        zb = fmaf(x0b[rr][d], w0, zb);
    }
    g_hkA[row * D_OUT + f] = __floats2half2_rn(ha, hb);
    g_h0 [row * D_OUT + f] = make_float2(za * ALPHA_F, zb * ALPHA_F);
}

// ---------------- 2) fused CSR-build + first SpMM iterate --------------------
// Warp per adjacency row. Metadata is built directly into SMEM (and mirrored to
// global for iterates 2-4), then the first propagation happens immediately —
// its gather latency hides under the DRAM-bound adjacency scan.
__global__ void csr_spmm1_kernel(const float* __restrict__ adj,
                                 const __half2* __restrict__ src,
                                 __half2* __restrict__ dst) {
    __shared__ int2  meta[8][MAX_NNZ];         // 8 KB: per-warp row metadata
    __shared__ float shs[8][32];
    __shared__ float shq[8][32];

    const int warp = threadIdx.x >> 5;
    const int lane = threadIdx.x & 31;
    const int r    = blockIdx.x * 8 + warp;

    // ---- CSR build ----
    const float4* row = (const float4*)(adj + (size_t)r * N_NODES);
    int2* out = (int2*)&g_cv4[(size_t)r * (MAX_NNZ / 2)];
    int base = 0;

    for (int ch = 0; ch < N_NODES / 128; ch += 2) {
        float4 vA = __ldcs(&row[ch * 32 + lane]);
        float4 vB = __ldcs(&row[(ch + 1) * 32 + lane]);
#pragma unroll
        for (int half = 0; half < 2; ++half) {
            const float4 v = half ? vB : vA;
            const bool any = (v.x != 0.f) | (v.y != 0.f) | (v.z != 0.f) | (v.w != 0.f);
            const unsigned am = __ballot_sync(0xffffffffu, any);
            if (am == 0u) continue;                 // uniform branch
            const float e[4] = {v.x, v.y, v.z, v.w};
#pragma unroll
            for (int k = 0; k < 4; ++k) {
                const bool nz = (e[k] != 0.0f);
                const unsigned m = __ballot_sync(0xffffffffu, nz);
                if (nz) {
                    int pos = base + __popc(m & ((1u << lane) - 1u));
                    if (pos < MAX_NNZ) {
                        const int2 cvp = make_int2((ch + half) * 128 + lane * 4 + k,
                                                   __float_as_int(e[k] * OMA_F));
                        meta[warp][pos] = cvp;      // smem copy for iterate 1
                        out[pos] = cvp;             // global copy for iterates 2-4
                    }
                }
                base += __popc(m);
            }
        }
    }
    int cnt  = base < MAX_NNZ ? base : MAX_NNZ;
    int cntp = (cnt + 7) & ~7;
    for (int j = cnt + lane; j < cntp; j += 32) {
        meta[warp][j] = make_int2(0, 0);
        out[j] = make_int2(0, 0);                    // val = 0 padding
    }
    if (lane == 0) g_cnt[r] = cntp;
    __syncwarp();

    // ---- SpMM iterate 1 (meta already in smem) ----
    const int4* mp = (const int4*)meta[warp];
    const int nIt = cntp >> 3;
    const float2 h0 = __ldg(&g_h0[r * D_OUT + lane]);
    float acc0 = h0.x, acc1 = h0.y;

    for (int it = 0; it < nIt; ++it) {
        const int4 a = mp[it * 4 + 0];
        const int4 b = mp[it * 4 + 1];
        const int4 c = mp[it * 4 + 2];
        const int4 d = mp[it * 4 + 3];

        const __half2 g0 = __ldg(&src[a.x * D_OUT + lane]);
        const __half2 g1 = __ldg(&src[a.z * D_OUT + lane]);
        const __half2 g2 = __ldg(&src[b.x * D_OUT + lane]);
        const __half2 g3 = __ldg(&src[b.z * D_OUT + lane]);
        const __half2 g4 = __ldg(&src[c.x * D_OUT + lane]);
        const __half2 g5 = __ldg(&src[c.z * D_OUT + lane]);
        const __half2 g6 = __ldg(&src[d.x * D_OUT + lane]);
        const __half2 g7 = __ldg(&src[d.z * D_OUT + lane]);

        float2 f;
        f = __half22float2(g0); acc0 = fmaf(__int_as_float(a.y), f.x, acc0); acc1 = fmaf(__int_as_float(a.y), f.y, acc1);
        f = __half22float2(g1); acc0 = fmaf(__int_as_float(a.w), f.x, acc0); acc1 = fmaf(__int_as_float(a.w), f.y, acc1);
        f = __half22float2(g2); acc0 = fmaf(__int_as_float(b.y), f.x, acc0); acc1 = fmaf(__int_as_float(b.y), f.y, acc1);
        f = __half22float2(g3); acc0 = fmaf(__int_as_float(b.w), f.x, acc0); acc1 = fmaf(__int_as_float(b.w), f.y, acc1);
        f = __half22float2(g4); acc0 = fmaf(__int_as_float(c.y), f.x, acc0); acc1 = fmaf(__int_as_float(c.y), f.y, acc1);
        f = __half22float2(g5); acc0 = fmaf(__int_as_float(c.w), f.x, acc0); acc1 = fmaf(__int_as_float(c.w), f.y, acc1);
        f = __half22float2(g6); acc0 = fmaf(__int_as_float(d.y), f.x, acc0); acc1 = fmaf(__int_as_float(d.y), f.y, acc1);
        f = __half22float2(g7); acc0 = fmaf(__int_as_float(d.w), f.x, acc0); acc1 = fmaf(__int_as_float(d.w), f.y, acc1);
    }

    dst[r * D_OUT + lane] = __floats2half2_rn(acc0, acc1);
    g_y[(size_t)r * C_CH + lane]             = acc0;
    g_y[(size_t)(N_NODES + r) * C_CH + lane] = acc1;

    shs[warp][lane] = acc0 + acc1;
    shq[warp][lane] = fmaf(acc0, acc0, acc1 * acc1);
    __syncthreads();
    if (warp == 0) {
        float s = 0.f;
#pragma unroll
        for (int w = 0; w < 8; ++w) s += shs[w][lane];
        g_psum[blockIdx.x * D_OUT + lane] = s;
    }
    if (warp == 1) {
        float q = 0.f;
#pragma unroll
        for (int w = 0; w < 8; ++w) q += shq[w][lane];
        g_psq[blockIdx.x * D_OUT + lane] = q;
    }
}

// ---------------- 3) SpMM iterate 2-4: smem-staged meta + BN partials --------
__global__ void spmm_kernel(const __half2* __restrict__ src,
                            __half2* __restrict__ dst, int kslice) {
    __shared__ int4  meta[8][MAX_NNZ / 2];     // 8 KB
    __shared__ float shs[8][32];
    __shared__ float shq[8][32];

    const int warp = threadIdx.x >> 5;
    const int lane = threadIdx.x & 31;
    const int r    = blockIdx.x * 8 + warp;

    const int4* __restrict__ cv = g_cv4 + (size_t)r * (MAX_NNZ / 2);
    meta[warp][lane]      = __ldg(&cv[lane]);
    meta[warp][lane + 32] = __ldg(&cv[lane + 32]);

    const int nIt = g_cnt[r] >> 3;
    const float2 h0 = __ldg(&g_h0[r * D_OUT + lane]);
    float acc0 = h0.x, acc1 = h0.y;
    __syncwarp();

    for (int it = 0; it < nIt; ++it) {
        const int4 a = meta[warp][it * 4 + 0];
        const int4 b = meta[warp][it * 4 + 1];
        const int4 c = meta[warp][it * 4 + 2];
        const int4 d = meta[warp][it * 4 + 3];

        const __half2 g0 = __ldg(&src[a.x * D_OUT + lane]);
        const __half2 g1 = __ldg(&src[a.z * D_OUT + lane]);
        const __half2 g2 = __ldg(&src[b.x * D_OUT + lane]);
        const __half2 g3 = __ldg(&src[b.z * D_OUT + lane]);
        const __half2 g4 = __ldg(&src[c.x * D_OUT + lane]);
        const __half2 g5 = __ldg(&src[c.z * D_OUT + lane]);
        const __half2 g6 = __ldg(&src[d.x * D_OUT + lane]);
        const __half2 g7 = __ldg(&src[d.z * D_OUT + lane]);

        float2 f;
        f = __half22float2(g0); acc0 = fmaf(__int_as_float(a.y), f.x, acc0); acc1 = fmaf(__int_as_float(a.y), f.y, acc1);
        f = __half22float2(g1); acc0 = fmaf(__int_as_float(a.w), f.x, acc0); acc1 = fmaf(__int_as_float(a.w), f.y, acc1);
        f = __half22float2(g2); acc0 = fmaf(__int_as_float(b.y), f.x, acc0); acc1 = fmaf(__int_as_float(b.y), f.y, acc1);
        f = __half22float2(g3); acc0 = fmaf(__int_as_float(b.w), f.x, acc0); acc1 = fmaf(__int_as_float(b.w), f.y, acc1);
        f = __half22float2(g4); acc0 = fmaf(__int_as_float(c.y), f.x, acc0); acc1 = fmaf(__int_as_float(c.y), f.y, acc1);
        f = __half22float2(g5); acc0 = fmaf(__int_as_float(c.w), f.x, acc0); acc1 = fmaf(__int_as_float(c.w), f.y, acc1);
        f = __half22float2(g6); acc0 = fmaf(__int_as_float(d.y), f.x, acc0); acc1 = fmaf(__int_as_float(d.y), f.y, acc1);
        f = __half22float2(g7); acc0 = fmaf(__int_as_float(d.w), f.x, acc0); acc1 = fmaf(__int_as_float(d.w), f.y, acc1);
    }

    dst[r * D_OUT + lane] = __floats2half2_rn(acc0, acc1);
    g_y[(size_t)r * C_CH + kslice * D_OUT + lane]             = acc0;
    g_y[(size_t)(N_NODES + r) * C_CH + kslice * D_OUT + lane] = acc1;

    shs[warp][lane] = acc0 + acc1;
    shq[warp][lane] = fmaf(acc0, acc0, acc1 * acc1);
    __syncthreads();
    if (warp == 0) {
        float s = 0.f;
#pragma unroll
        for (int w = 0; w < 8; ++w) s += shs[w][lane];
        g_psum[(kslice * SPMM_BLOCKS + blockIdx.x) * D_OUT + lane] = s;
    }
    if (warp == 1) {
        float q = 0.f;
#pragma unroll
        for (int w = 0; w < 8; ++w) q += shq[w][lane];
        g_psq[(kslice * SPMM_BLOCKS + blockIdx.x) * D_OUT + lane] = q;
    }
}

// ---------------- 4) finalize BN params ----------------
__global__ void bn_final_kernel(const float* __restrict__ gamma,
                                const float* __restrict__ beta) {
    __shared__ float ss[1024], qq[1024];
    const int c = threadIdx.x & 127;            // channel
    const int h = threadIdx.x >> 7;             // 0..7
    const int slice = c >> 5, lane = c & 31;

    float s = 0.f, q = 0.f;
    for (int b = h; b < SPMM_BLOCKS; b += 8) {
        s += g_psum[(slice * SPMM_BLOCKS + b) * D_OUT + lane];
        q += g_psq [(slice * SPMM_BLOCKS + b) * D_OUT + lane];
    }
    ss[threadIdx.x] = s;
    qq[threadIdx.x] = q;
    __syncthreads();
    if (h == 0) {
        s = 0.f; q = 0.f;
#pragma unroll
        for (int w = 0; w < 8; ++w) { s += ss[c + 128 * w]; q += qq[c + 128 * w]; }
        const float inv  = 1.0f / (float)NSAMP;
        const float mean = s * inv;
        const float var  = q * inv - mean * mean;
        const float sc   = gamma[c] * rsqrtf(var + BN_EPS_F);
        g_scale[c] = sc;
        g_shift[c] = beta[c] - mean * sc;
    }
}

// ---------------- 5) normalize + ReLU ----------------
__global__ void norm_kernel(float* __restrict__ out) {
    const int idx = blockIdx.x * blockDim.x + threadIdx.x;   // float4 index
    float4 v = ((const float4*)g_y)[idx];
    const int c0 = (idx & 31) * 4;
    v.x = fmaxf(0.f, fmaf(v.x, g_scale[c0 + 0], g_shift[c0 + 0]));
    v.y = fmaxf(0.f, fmaf(v.y, g_scale[c0 + 1], g_shift[c0 + 1]));
    v.z = fmaxf(0.f, fmaf(v.z, g_scale[c0 + 2], g_shift[c0 + 2]));
    v.w = fmaxf(0.f, fmaf(v.w, g_scale[c0 + 3], g_shift[c0 + 3]));
    ((float4*)out)[idx] = v;
}

// ---------------- launch ----------------
extern "C" void kernel_launch(void* const* d_in, const int* in_sizes, int n_in,
                              void* d_out, int out_size) {
    const float* x     = (const float*)d_in[0];
    const float* x0    = (const float*)d_in[1];
    const float* adj   = (const float*)d_in[2];
    const float* W     = (const float*)d_in[3];
    const float* W0    = (const float*)d_in[4];
    const float* gamma = (const float*)d_in[5];
    const float* beta  = (const float*)d_in[6];
    float* out = (float*)d_out;

    __half2 *hkA, *hkB;
    cudaGetSymbolAddress((void**)&hkA, g_hkA);
    cudaGetSymbolAddress((void**)&hkB, g_hkB);

    gemm_kernel<<<N_NODES / 8, 256>>>(x, x0, W, W0);
    csr_spmm1_kernel<<<N_NODES / 8, 256>>>(adj, hkA, hkB);   // scan + iterate 1

    spmm_kernel<<<SPMM_BLOCKS, 256>>>(hkB, hkA, 1);
    spmm_kernel<<<SPMM_BLOCKS, 256>>>(hkA, hkB, 2);
    spmm_kernel<<<SPMM_BLOCKS, 256>>>(hkB, hkA, 3);

    bn_final_kernel<<<1, 1024>>>(gamma, beta);
    norm_kernel<<<(NSAMP * C_CH / 4) / 256, 256>>>(out);
}

// round 8
// speedup vs baseline: 1.1256x; 1.0066x over previous
#include <cuda_runtime.h>
#include <cuda_fp16.h>

#define N_NODES   8192
#define B_BATCH   2
#define D_IN      64
#define D_OUT     32
#define K_ITERS   4
#define C_CH      (K_ITERS * D_OUT)   // 128
#define ALPHA_F   0.1f
#define OMA_F     0.9f
#define BN_EPS_F  1e-5f
#define MAX_NNZ   128
#define NSAMP     (B_BATCH * N_NODES)
#define SPMM_BLOCKS 1024               // 8 rows per block, warp per row

// ---------------- device scratch ----------------
__device__ __half2 g_hkA[N_NODES * D_OUT];               // ping [n][f] -> (b0,b1)
__device__ __half2 g_hkB[N_NODES * D_OUT];               // pong
__device__ float2  g_h0 [N_NODES * D_OUT];               // alpha*(x0@W0)
__device__ int4    g_cv4[(size_t)N_NODES * MAX_NNZ / 2]; // {col,val,col,val}
__device__ int     g_cnt[N_NODES];                       // padded to mult of 8
__device__ float   g_y  [(size_t)B_BATCH * N_NODES * C_CH];
__device__ float   g_psum[K_ITERS * SPMM_BLOCKS * D_OUT];
__device__ float   g_psq [K_ITERS * SPMM_BLOCKS * D_OUT];
__device__ float   g_scale[C_CH];
__device__ float   g_shift[C_CH];

// ---------------- 1) projections, both batches per thread ----------------
__global__ void gemm_kernel(const float* __restrict__ x,
                            const float* __restrict__ x0,
                            const float* __restrict__ W,
                            const float* __restrict__ W0) {
    __shared__ float Ws [D_IN * D_OUT];
    __shared__ float W0s[D_IN * D_OUT];
    __shared__ float xa [8][D_IN], xb [8][D_IN];
    __shared__ float x0a[8][D_IN], x0b[8][D_IN];

    const int t = threadIdx.x;
    const int rowBase = blockIdx.x * 8;

    for (int i = t; i < D_IN * D_OUT; i += 256) { Ws[i] = W[i]; W0s[i] = W0[i]; }
    for (int i = t; i < 8 * D_IN; i += 256) {
        const int r = rowBase + (i >> 6);
        const int d = i & 63;
        xa [i >> 6][d] = x [(size_t)r * D_IN + d];
        xb [i >> 6][d] = x [(size_t)(N_NODES + r) * D_IN + d];
        x0a[i >> 6][d] = x0[(size_t)r * D_IN + d];
        x0b[i >> 6][d] = x0[(size_t)(N_NODES + r) * D_IN + d];
    }
    __syncthreads();

    const int rr = t >> 5;
    const int f  = t & 31;
    const int row = rowBase + rr;
    float ha = 0.f, hb = 0.f, za = 0.f, zb = 0.f;
#pragma unroll
    for (int d = 0; d < D_IN; ++d) {
        const float w  = Ws [d * D_OUT + f];
        const float w0 = W0s[d * D_OUT + f];
        ha = fmaf(xa [rr][d], w,  ha);
        hb = fmaf(xb [rr][d], w,  hb);
        za = fmaf(x0a[rr][d], w0, za);
        zb = fmaf(x0b[rr][d], w0, zb);
    }
    g_hkA[row * D_OUT + f] = __floats2half2_rn(ha, hb);
    g_h0 [row * D_OUT + f] = make_float2(za * ALPHA_F, zb * ALPHA_F);
}

// ---------------- 2) fused CSR-build + first SpMM iterate --------------------
__global__ void csr_spmm1_kernel(const float* __restrict__ adj,
                                 const __half2* __restrict__ src,
                                 __half2* __restrict__ dst) {
    __shared__ int2  meta[8][MAX_NNZ];         // 8 KB: per-warp row metadata
    __shared__ float shs[8][32];
    __shared__ float shq[8][32];

    const int warp = threadIdx.x >> 5;
    const int lane = threadIdx.x & 31;
    const int r    = blockIdx.x * 8 + warp;

    // ---- CSR build ----
    const float4* row = (const float4*)(adj + (size_t)r * N_NODES);
    int2* out = (int2*)&g_cv4[(size_t)r * (MAX_NNZ / 2)];
    int base = 0;

    for (int ch = 0; ch < N_NODES / 128; ch += 2) {
        float4 vA = __ldcs(&row[ch * 32 + lane]);
        float4 vB = __ldcs(&row[(ch + 1) * 32 + lane]);
#pragma unroll
        for (int half = 0; half < 2; ++half) {
            const float4 v = half ? vB : vA;
            const bool any = (v.x != 0.f) | (v.y != 0.f) | (v.z != 0.f) | (v.w != 0.f);
            const unsigned am = __ballot_sync(0xffffffffu, any);
            if (am == 0u) continue;                 // uniform branch
            const float e[4] = {v.x, v.y, v.z, v.w};
#pragma unroll
            for (int k = 0; k < 4; ++k) {
                const bool nz = (e[k] != 0.0f);
                const unsigned m = __ballot_sync(0xffffffffu, nz);
                if (nz) {
                    int pos = base + __popc(m & ((1u << lane) - 1u));
                    if (pos < MAX_NNZ) {
                        const int2 cvp = make_int2((ch + half) * 128 + lane * 4 + k,
                                                   __float_as_int(e[k] * OMA_F));
                        meta[warp][pos] = cvp;      // smem copy for iterate 1
                        out[pos] = cvp;             // global copy for iterates 2-4
                    }
                }
                base += __popc(m);
            }
        }
    }
    int cnt  = base < MAX_NNZ ? base : MAX_NNZ;
    int cntp = (cnt + 7) & ~7;
    for (int j = cnt + lane; j < cntp; j += 32) {
        meta[warp][j] = make_int2(0, 0);
        out[j] = make_int2(0, 0);                    // val = 0 padding
    }
    if (lane == 0) g_cnt[r] = cntp;
    __syncwarp();

    // ---- SpMM iterate 1 (meta already in smem) ----
    const int4* mp = (const int4*)meta[warp];
    const int nIt = cntp >> 3;
    const float2 h0 = __ldg(&g_h0[r * D_OUT + lane]);
    float acc0 = h0.x, acc1 = h0.y;

    for (int it = 0; it < nIt; ++it) {
        const int4 a = mp[it * 4 + 0];
        const int4 b = mp[it * 4 + 1];
        const int4 c = mp[it * 4 + 2];
        const int4 d = mp[it * 4 + 3];

        const __half2 g0 = __ldg(&src[a.x * D_OUT + lane]);
        const __half2 g1 = __ldg(&src[a.z * D_OUT + lane]);
        const __half2 g2 = __ldg(&src[b.x * D_OUT + lane]);
        const __half2 g3 = __ldg(&src[b.z * D_OUT + lane]);
        const __half2 g4 = __ldg(&src[c.x * D_OUT + lane]);
        const __half2 g5 = __ldg(&src[c.z * D_OUT + lane]);
        const __half2 g6 = __ldg(&src[d.x * D_OUT + lane]);
        const __half2 g7 = __ldg(&src[d.z * D_OUT + lane]);

        float2 f;
        f = __half22float2(g0); acc0 = fmaf(__int_as_float(a.y), f.x, acc0); acc1 = fmaf(__int_as_float(a.y), f.y, acc1);
        f = __half22float2(g1); acc0 = fmaf(__int_as_float(a.w), f.x, acc0); acc1 = fmaf(__int_as_float(a.w), f.y, acc1);
        f = __half22float2(g2); acc0 = fmaf(__int_as_float(b.y), f.x, acc0); acc1 = fmaf(__int_as_float(b.y), f.y, acc1);
        f = __half22float2(g3); acc0 = fmaf(__int_as_float(b.w), f.x, acc0); acc1 = fmaf(__int_as_float(b.w), f.y, acc1);
        f = __half22float2(g4); acc0 = fmaf(__int_as_float(c.y), f.x, acc0); acc1 = fmaf(__int_as_float(c.y), f.y, acc1);
        f = __half22float2(g5); acc0 = fmaf(__int_as_float(c.w), f.x, acc0); acc1 = fmaf(__int_as_float(c.w), f.y, acc1);
        f = __half22float2(g6); acc0 = fmaf(__int_as_float(d.y), f.x, acc0); acc1 = fmaf(__int_as_float(d.y), f.y, acc1);
        f = __half22float2(g7); acc0 = fmaf(__int_as_float(d.w), f.x, acc0); acc1 = fmaf(__int_as_float(d.w), f.y, acc1);
    }

    dst[r * D_OUT + lane] = __floats2half2_rn(acc0, acc1);
    g_y[(size_t)r * C_CH + lane]             = acc0;
    g_y[(size_t)(N_NODES + r) * C_CH + lane] = acc1;

    shs[warp][lane] = acc0 + acc1;
    shq[warp][lane] = fmaf(acc0, acc0, acc1 * acc1);
    __syncthreads();
    if (warp == 0) {
        float s = 0.f;
#pragma unroll
        for (int w = 0; w < 8; ++w) s += shs[w][lane];
        g_psum[blockIdx.x * D_OUT + lane] = s;
    }
    if (warp == 1) {
        float q = 0.f;
#pragma unroll
        for (int w = 0; w < 8; ++w) q += shq[w][lane];
        g_psq[blockIdx.x * D_OUT + lane] = q;
    }
}

// ---------------- 3) SpMM iterate 2-4: 32-reg cap, 4-nnz sub-groups ----------
__global__ void __launch_bounds__(256, 8)
spmm_kernel(const __half2* __restrict__ src,
            __half2* __restrict__ dst, int kslice, int writeDst) {
    __shared__ int4  meta[8][MAX_NNZ / 2];     // 8 KB
    __shared__ float shs[8][32];
    __shared__ float shq[8][32];

    const int warp = threadIdx.x >> 5;
    const int lane = threadIdx.x & 31;
    const int r    = blockIdx.x * 8 + warp;

    const int4* __restrict__ cv = g_cv4 + (size_t)r * (MAX_NNZ / 2);
    meta[warp][lane]      = __ldg(&cv[lane]);
    meta[warp][lane + 32] = __ldg(&cv[lane + 32]);

    const int nIt = g_cnt[r] >> 2;             // groups of 4 nnz
    const float2 h0 = __ldg(&g_h0[r * D_OUT + lane]);
    float acc0 = h0.x, acc1 = h0.y;
    __syncwarp();

#pragma unroll 2
    for (int it = 0; it < nIt; ++it) {
        const int4 a = meta[warp][it * 2 + 0];   // uniform LDS.128
        const int4 b = meta[warp][it * 2 + 1];

        const __half2 g0 = __ldg(&src[a.x * D_OUT + lane]);
        const __half2 g1 = __ldg(&src[a.z * D_OUT + lane]);
        const __half2 g2 = __ldg(&src[b.x * D_OUT + lane]);
        const __half2 g3 = __ldg(&src[b.z * D_OUT + lane]);

        float2 f;
        f = __half22float2(g0); acc0 = fmaf(__int_as_float(a.y), f.x, acc0); acc1 = fmaf(__int_as_float(a.y), f.y, acc1);
        f = __half22float2(g1); acc0 = fmaf(__int_as_float(a.w), f.x, acc0); acc1 = fmaf(__int_as_float(a.w), f.y, acc1);
        f = __half22float2(g2); acc0 = fmaf(__int_as_float(b.y), f.x, acc0); acc1 = fmaf(__int_as_float(b.y), f.y, acc1);
        f = __half22float2(g3); acc0 = fmaf(__int_as_float(b.w), f.x, acc0); acc1 = fmaf(__int_as_float(b.w), f.y, acc1);
    }

    if (writeDst)
        dst[r * D_OUT + lane] = __floats2half2_rn(acc0, acc1);
    g_y[(size_t)r * C_CH + kslice * D_OUT + lane]             = acc0;
    g_y[(size_t)(N_NODES + r) * C_CH + kslice * D_OUT + lane] = acc1;

    shs[warp][lane] = acc0 + acc1;
    shq[warp][lane] = fmaf(acc0, acc0, acc1 * acc1);
    __syncthreads();
    if (warp == 0) {
        float s = 0.f;
#pragma unroll
        for (int w = 0; w < 8; ++w) s += shs[w][lane];
        g_psum[(kslice * SPMM_BLOCKS + blockIdx.x) * D_OUT + lane] = s;
    }
    if (warp == 1) {
        float q = 0.f;
#pragma unroll
        for (int w = 0; w < 8; ++w) q += shq[w][lane];
        g_psq[(kslice * SPMM_BLOCKS + blockIdx.x) * D_OUT + lane] = q;
    }
}

// ---------------- 4) finalize BN params ----------------
__global__ void bn_final_kernel(const float* __restrict__ gamma,
                                const float* __restrict__ beta) {
    __shared__ float ss[1024], qq[1024];
    const int c = threadIdx.x & 127;            // channel
    const int h = threadIdx.x >> 7;             // 0..7
    const int slice = c >> 5, lane = c & 31;

    float s = 0.f, q = 0.f;
    for (int b = h; b < SPMM_BLOCKS; b += 8) {
        s += g_psum[(slice * SPMM_BLOCKS + b) * D_OUT + lane];
        q += g_psq [(slice * SPMM_BLOCKS + b) * D_OUT + lane];
    }
    ss[threadIdx.x] = s;
    qq[threadIdx.x] = q;
    __syncthreads();
    if (h == 0) {
        s = 0.f; q = 0.f;
#pragma unroll
        for (int w = 0; w < 8; ++w) { s += ss[c + 128 * w]; q += qq[c + 128 * w]; }
        const float inv  = 1.0f / (float)NSAMP;
        const float mean = s * inv;
        const float var  = q * inv - mean * mean;
        const float sc   = gamma[c] * rsqrtf(var + BN_EPS_F);
        g_scale[c] = sc;
        g_shift[c] = beta[c] - mean * sc;
    }
}

// ---------------- 5) normalize + ReLU ----------------
__global__ void norm_kernel(float* __restrict__ out) {
    const int idx = blockIdx.x * blockDim.x + threadIdx.x;   // float4 index
    float4 v = ((const float4*)g_y)[idx];
    const int c0 = (idx & 31) * 4;
    v.x = fmaxf(0.f, fmaf(v.x, g_scale[c0 + 0], g_shift[c0 + 0]));
    v.y = fmaxf(0.f, fmaf(v.y, g_scale[c0 + 1], g_shift[c0 + 1]));
    v.z = fmaxf(0.f, fmaf(v.z, g_scale[c0 + 2], g_shift[c0 + 2]));
    v.w = fmaxf(0.f, fmaf(v.w, g_scale[c0 + 3], g_shift[c0 + 3]));
    ((float4*)out)[idx] = v;
}

// ---------------- launch ----------------
extern "C" void kernel_launch(void* const* d_in, const int* in_sizes, int n_in,
                              void* d_out, int out_size) {
    const float* x     = (const float*)d_in[0];
    const float* x0    = (const float*)d_in[1];
    const float* adj   = (const float*)d_in[2];
    const float* W     = (const float*)d_in[3];
    const float* W0    = (const float*)d_in[4];
    const float* gamma = (const float*)d_in[5];
    const float* beta  = (const float*)d_in[6];
    float* out = (float*)d_out;

    __half2 *hkA, *hkB;
    cudaGetSymbolAddress((void**)&hkA, g_hkA);
    cudaGetSymbolAddress((void**)&hkB, g_hkB);

    gemm_kernel<<<N_NODES / 8, 256>>>(x, x0, W, W0);
    csr_spmm1_kernel<<<N_NODES / 8, 256>>>(adj, hkA, hkB);   // scan + iterate 1

    spmm_kernel<<<SPMM_BLOCKS, 256>>>(hkB, hkA, 1, 1);
    spmm_kernel<<<SPMM_BLOCKS, 256>>>(hkA, hkB, 2, 1);
    spmm_kernel<<<SPMM_BLOCKS, 256>>>(hkB, hkA, 3, 0);       // last: no dst write

    bn_final_kernel<<<1, 1024>>>(gamma, beta);
    norm_kernel<<<(NSAMP * C_CH / 4) / 256, 256>>>(out);
}

// round 9
// speedup vs baseline: 1.1399x; 1.0128x over previous
#include <cuda_runtime.h>
#include <cuda_fp16.h>

#define N_NODES   8192
#define B_BATCH   2
#define D_IN      64
#define D_OUT     32
#define K_ITERS   4
#define C_CH      (K_ITERS * D_OUT)   // 128
#define ALPHA_F   0.1f
#define OMA_F     0.9f
#define BN_EPS_F  1e-5f
#define MAX_NNZ   128
#define NSAMP     (B_BATCH * N_NODES)
#define NBLK      1024                 // 8 rows per block, warp per row

// ---------------- device scratch ----------------
__device__ __half2 g_hkA[N_NODES * D_OUT];               // ping [n][f] -> (b0,b1)
__device__ __half2 g_hkB[N_NODES * D_OUT];               // pong
__device__ float2  g_h0 [N_NODES * D_OUT];               // alpha*(x0@W0)
__device__ int4    g_cv4[(size_t)N_NODES * MAX_NNZ / 2]; // {col*32,val}x2
__device__ int     g_cnt[N_NODES];                       // padded to mult of 8
__device__ float   g_y  [(size_t)B_BATCH * N_NODES * C_CH];
__device__ float   g_psum[K_ITERS * NBLK * D_OUT];
__device__ float   g_psq [K_ITERS * NBLK * D_OUT];
__device__ float   g_scale[C_CH];
__device__ float   g_shift[C_CH];
__device__ int     g_bar = 0;                            // barrier arrivals
__device__ int     g_gen = 0;                            // barrier generation

// device-wide sense barrier (all NBLK blocks resident by construction)
__device__ __forceinline__ void grid_sync() {
    __syncthreads();
    if (threadIdx.x == 0) {
        __threadfence();
        const int my = *(volatile int*)&g_gen;
        if (atomicAdd(&g_bar, 1) == NBLK - 1) {
            atomicExch(&g_bar, 0);
            __threadfence();
            atomicAdd(&g_gen, 1);
        } else {
            while (*(volatile int*)&g_gen == my) { }
        }
        __threadfence();
    }
    __syncthreads();
}

// ---------------- 1) projections, both batches per thread ----------------
__global__ void gemm_kernel(const float* __restrict__ x,
                            const float* __restrict__ x0,
                            const float* __restrict__ W,
                            const float* __restrict__ W0) {
    __shared__ float Ws [D_IN * D_OUT];
    __shared__ float W0s[D_IN * D_OUT];
    __shared__ float xa [8][D_IN], xb [8][D_IN];
    __shared__ float x0a[8][D_IN], x0b[8][D_IN];

    const int t = threadIdx.x;
    const int rowBase = blockIdx.x * 8;

    for (int i = t; i < D_IN * D_OUT; i += 256) { Ws[i] = W[i]; W0s[i] = W0[i]; }
    for (int i = t; i < 8 * D_IN; i += 256) {
        const int r = rowBase + (i >> 6);
        const int d = i & 63;
        xa [i >> 6][d] = x [(size_t)r * D_IN + d];
        xb [i >> 6][d] = x [(size_t)(N_NODES + r) * D_IN + d];
        x0a[i >> 6][d] = x0[(size_t)r * D_IN + d];
        x0b[i >> 6][d] = x0[(size_t)(N_NODES + r) * D_IN + d];
    }
    __syncthreads();

    const int rr = t >> 5;
    const int f  = t & 31;
    const int row = rowBase + rr;
    float ha = 0.f, hb = 0.f, za = 0.f, zb = 0.f;
#pragma unroll
    for (int d = 0; d < D_IN; ++d) {
        const float w  = Ws [d * D_OUT + f];
        const float w0 = W0s[d * D_OUT + f];
        ha = fmaf(xa [rr][d], w,  ha);
        hb = fmaf(xb [rr][d], w,  hb);
        za = fmaf(x0a[rr][d], w0, za);
        zb = fmaf(x0b[rr][d], w0, zb);
    }
    g_hkA[row * D_OUT + f] = __floats2half2_rn(ha, hb);
    g_h0 [row * D_OUT + f] = make_float2(za * ALPHA_F, zb * ALPHA_F);
}

// ---------------- 2) fused CSR-build + first SpMM iterate --------------------
__global__ void csr_spmm1_kernel(const float* __restrict__ adj) {
    __shared__ int2  meta[8][MAX_NNZ];         // 8 KB: per-warp row metadata
    __shared__ float shs[8][32];
    __shared__ float shq[8][32];

    const int warp = threadIdx.x >> 5;
    const int lane = threadIdx.x & 31;
    const int r    = blockIdx.x * 8 + warp;

    // ---- CSR build (col stored pre-multiplied by D_OUT) ----
    const float4* row = (const float4*)(adj + (size_t)r * N_NODES);
    int2* out = (int2*)&g_cv4[(size_t)r * (MAX_NNZ / 2)];
    int base = 0;

    for (int ch = 0; ch < N_NODES / 128; ch += 2) {
        float4 vA = __ldcs(&row[ch * 32 + lane]);
        float4 vB = __ldcs(&row[(ch + 1) * 32 + lane]);
#pragma unroll
        for (int half = 0; half < 2; ++half) {
            const float4 v = half ? vB : vA;
            const bool any = (v.x != 0.f) | (v.y != 0.f) | (v.z != 0.f) | (v.w != 0.f);
            const unsigned am = __ballot_sync(0xffffffffu, any);
            if (am == 0u) continue;                 // uniform branch
            const float e[4] = {v.x, v.y, v.z, v.w};
#pragma unroll
            for (int k = 0; k < 4; ++k) {
                const bool nz = (e[k] != 0.0f);
                const unsigned m = __ballot_sync(0xffffffffu, nz);
                if (nz) {
                    int pos = base + __popc(m & ((1u << lane) - 1u));
                    if (pos < MAX_NNZ) {
                        const int2 cvp = make_int2(((ch + half) * 128 + lane * 4 + k) << 5,
                                                   __float_as_int(e[k] * OMA_F));
                        meta[warp][pos] = cvp;      // smem copy for iterate 1
                        out[pos] = cvp;             // global copy for iterates 2-4
                    }
                }
                base += __popc(m);
            }
        }
    }
    int cnt  = base < MAX_NNZ ? base : MAX_NNZ;
    int cntp = (cnt + 7) & ~7;
    for (int j = cnt + lane; j < cntp; j += 32) {
        meta[warp][j] = make_int2(0, 0);
        out[j] = make_int2(0, 0);                    // val = 0 padding
    }
    if (lane == 0) g_cnt[r] = cntp;
    __syncwarp();

    // ---- SpMM iterate 1 (meta already in smem) ----
    const int4* mp = (const int4*)meta[warp];
    const int nIt = cntp >> 3;
    const float2 h0 = __ldg(&g_h0[r * D_OUT + lane]);
    float acc0 = h0.x, acc1 = h0.y;
    const __half2* __restrict__ src = g_hkA;

    for (int it = 0; it < nIt; ++it) {
        const int4 a = mp[it * 4 + 0];
        const int4 b = mp[it * 4 + 1];
        const int4 c = mp[it * 4 + 2];
        const int4 d = mp[it * 4 + 3];

        const __half2 g0 = __ldg(&src[a.x + lane]);
        const __half2 g1 = __ldg(&src[a.z + lane]);
        const __half2 g2 = __ldg(&src[b.x + lane]);
        const __half2 g3 = __ldg(&src[b.z + lane]);
        const __half2 g4 = __ldg(&src[c.x + lane]);
        const __half2 g5 = __ldg(&src[c.z + lane]);
        const __half2 g6 = __ldg(&src[d.x + lane]);
        const __half2 g7 = __ldg(&src[d.z + lane]);

        float2 f;
        f = __half22float2(g0); acc0 = fmaf(__int_as_float(a.y), f.x, acc0); acc1 = fmaf(__int_as_float(a.y), f.y, acc1);
        f = __half22float2(g1); acc0 = fmaf(__int_as_float(a.w), f.x, acc0); acc1 = fmaf(__int_as_float(a.w), f.y, acc1);
        f = __half22float2(g2); acc0 = fmaf(__int_as_float(b.y), f.x, acc0); acc1 = fmaf(__int_as_float(b.y), f.y, acc1);
        f = __half22float2(g3); acc0 = fmaf(__int_as_float(b.w), f.x, acc0); acc1 = fmaf(__int_as_float(b.w), f.y, acc1);
        f = __half22float2(g4); acc0 = fmaf(__int_as_float(c.y), f.x, acc0); acc1 = fmaf(__int_as_float(c.y), f.y, acc1);
        f = __half22float2(g5); acc0 = fmaf(__int_as_float(c.w), f.x, acc0); acc1 = fmaf(__int_as_float(c.w), f.y, acc1);
        f = __half22float2(g6); acc0 = fmaf(__int_as_float(d.y), f.x, acc0); acc1 = fmaf(__int_as_float(d.y), f.y, acc1);
        f = __half22float2(g7); acc0 = fmaf(__int_as_float(d.w), f.x, acc0); acc1 = fmaf(__int_as_float(d.w), f.y, acc1);
    }

    g_hkB[r * D_OUT + lane] = __floats2half2_rn(acc0, acc1);
    g_y[(size_t)r * C_CH + lane]             = acc0;
    g_y[(size_t)(N_NODES + r) * C_CH + lane] = acc1;

    shs[warp][lane] = acc0 + acc1;
    shq[warp][lane] = fmaf(acc0, acc0, acc1 * acc1);
    __syncthreads();
    if (warp == 0) {
        float s = 0.f;
#pragma unroll
        for (int w = 0; w < 8; ++w) s += shs[w][lane];
        g_psum[blockIdx.x * D_OUT + lane] = s;
    }
    if (warp == 1) {
        float q = 0.f;
#pragma unroll
        for (int w = 0; w < 8; ++w) q += shq[w][lane];
        g_psq[blockIdx.x * D_OUT + lane] = q;
    }
}

// ---------------- 3) persistent: iterates 2-4 + BN + norm + ReLU -------------
__global__ void __launch_bounds__(256, 8)
post_kernel(const float* __restrict__ gamma,
            const float* __restrict__ beta,
            float* __restrict__ out) {
    __shared__ int4  meta[8][MAX_NNZ / 2];     // 8 KB
    __shared__ float shs[8][32];
    __shared__ float shq[8][32];

    const int warp = threadIdx.x >> 5;
    const int lane = threadIdx.x & 31;
    const int r    = blockIdx.x * 8 + warp;

    // stage metadata ONCE for all 3 iterates
    const int4* __restrict__ cv = g_cv4 + (size_t)r * (MAX_NNZ / 2);
    meta[warp][lane]      = __ldg(&cv[lane]);
    meta[warp][lane + 32] = __ldg(&cv[lane + 32]);
    const int nIt = g_cnt[r] >> 2;             // groups of 4 nnz
    const float2 h0 = __ldg(&g_h0[r * D_OUT + lane]);
    __syncwarp();

    for (int k = 1; k < 4; ++k) {
        const __half2* __restrict__ src = (k & 1) ? g_hkB : g_hkA;
        __half2* __restrict__ dst       = (k & 1) ? g_hkA : g_hkB;

        float acc0 = h0.x, acc1 = h0.y;
#pragma unroll 2
        for (int it = 0; it < nIt; ++it) {
            const int4 a = meta[warp][it * 2 + 0];   // uniform LDS.128
            const int4 b = meta[warp][it * 2 + 1];

            const __half2 g0 = __ldg(&src[a.x + lane]);
            const __half2 g1 = __ldg(&src[a.z + lane]);
            const __half2 g2 = __ldg(&src[b.x + lane]);
            const __half2 g3 = __ldg(&src[b.z + lane]);

            float2 f;
            f = __half22float2(g0); acc0 = fmaf(__int_as_float(a.y), f.x, acc0); acc1 = fmaf(__int_as_float(a.y), f.y, acc1);
            f = __half22float2(g1); acc0 = fmaf(__int_as_float(a.w), f.x, acc0); acc1 = fmaf(__int_as_float(a.w), f.y, acc1);
            f = __half22float2(g2); acc0 = fmaf(__int_as_float(b.y), f.x, acc0); acc1 = fmaf(__int_as_float(b.y), f.y, acc1);
            f = __half22float2(g3); acc0 = fmaf(__int_as_float(b.w), f.x, acc0); acc1 = fmaf(__int_as_float(b.w), f.y, acc1);
        }

        if (k < 3)
            dst[r * D_OUT + lane] = __floats2half2_rn(acc0, acc1);
        g_y[(size_t)r * C_CH + k * D_OUT + lane]             = acc0;
        g_y[(size_t)(N_NODES + r) * C_CH + k * D_OUT + lane] = acc1;

        shs[warp][lane] = acc0 + acc1;
        shq[warp][lane] = fmaf(acc0, acc0, acc1 * acc1);
        __syncthreads();
        if (warp == 0) {
            float s = 0.f;
#pragma unroll
            for (int w = 0; w < 8; ++w) s += shs[w][lane];
            g_psum[(k * NBLK + blockIdx.x) * D_OUT + lane] = s;
        }
        if (warp == 1) {
            float q = 0.f;
#pragma unroll
            for (int w = 0; w < 8; ++w) q += shq[w][lane];
            g_psq[(k * NBLK + blockIdx.x) * D_OUT + lane] = q;
        }
        grid_sync();                           // hk + partials visible everywhere
    }

    // ---- BN finalize: block c (c < 128) owns channel c ----
    if (blockIdx.x < C_CH) {
        const int c     = blockIdx.x;
        const int slice = c >> 5;
        const int ln    = c & 31;
        const int t     = threadIdx.x;
        float s = 0.f, q = 0.f;
        for (int j = t; j < NBLK; j += 256) {
            s += g_psum[(slice * NBLK + j) * D_OUT + ln];
            q += g_psq [(slice * NBLK + j) * D_OUT + ln];
        }
        float* fs = &shs[0][0];
        float* fq = &shq[0][0];
        fs[t] = s; fq[t] = q;
        __syncthreads();
        if (t < 128) { fs[t] += fs[t + 128]; fq[t] += fq[t + 128]; }
        __syncthreads();
        if (t < 64)  { fs[t] += fs[t + 64];  fq[t] += fq[t + 64];  }
        __syncthreads();
        if (t < 32) {
            s = fs[t] + fs[t + 32];
            q = fq[t] + fq[t + 32];
#pragma unroll
            for (int off = 16; off > 0; off >>= 1) {
                s += __shfl_down_sync(0xffffffffu, s, off);
                q += __shfl_down_sync(0xffffffffu, q, off);
            }
            if (t == 0) {
                const float inv  = 1.0f / (float)NSAMP;
                const float mean = s * inv;
                const float var  = q * inv - mean * mean;
                const float sc   = gamma[c] * rsqrtf(var + BN_EPS_F);
                g_scale[c] = sc;
                g_shift[c] = beta[c] - mean * sc;
            }
        }
    }
    grid_sync();                               // scale/shift visible everywhere

    // ---- normalize + ReLU: 512 float4 per block ----
    const float4* yv = (const float4*)g_y;
    float4*       ov = (float4*)out;
#pragma unroll
    for (int i = 0; i < 2; ++i) {
        const int idx = blockIdx.x * 512 + i * 256 + threadIdx.x;
        float4 v = yv[idx];
        const int c0 = (idx & 31) * 4;
        v.x = fmaxf(0.f, fmaf(v.x, g_scale[c0 + 0], g_shift[c0 + 0]));
        v.y = fmaxf(0.f, fmaf(v.y, g_scale[c0 + 1], g_shift[c0 + 1]));
        v.z = fmaxf(0.f, fmaf(v.z, g_scale[c0 + 2], g_shift[c0 + 2]));
        v.w = fmaxf(0.f, fmaf(v.w, g_scale[c0 + 3], g_shift[c0 + 3]));
        ov[idx] = v;
    }
}

// ---------------- launch ----------------
extern "C" void kernel_launch(void* const* d_in, const int* in_sizes, int n_in,
                              void* d_out, int out_size) {
    const float* x     = (const float*)d_in[0];
    const float* x0    = (const float*)d_in[1];
    const float* adj   = (const float*)d_in[2];
    const float* W     = (const float*)d_in[3];
    const float* W0    = (const float*)d_in[4];
    const float* gamma = (const float*)d_in[5];
    const float* beta  = (const float*)d_in[6];
    float* out = (float*)d_out;

    gemm_kernel<<<N_NODES / 8, 256>>>(x, x0, W, W0);
    csr_spmm1_kernel<<<N_NODES / 8, 256>>>(adj);     // scan + iterate 1
    post_kernel<<<NBLK, 256>>>(gamma, beta, out);    // iterates 2-4 + BN + norm
}